// round 9
// baseline (speedup 1.0000x reference)
#include <cuda_runtime.h>
#include <float.h>

// Batched Jacobi-preconditioned FISTA (+ residual-increase restart) on the
// dual of a ramp-constrained QP. One warp per batch item; 4 elements/lane.
// Gradient step is an affine tridiagonal stencil with per-element steps
// step_i = 0.5/(m_i + m_{i+1})  (valid since A <= 2 diag(A) by diagonal
// dominance); diagonal stencil coefficient is exactly 0.5 for all i.
// Halos exchange the prox output n (not y); y-halos are reconstructed
// locally with the block-constant beta -> short cross-lane critical path.
#define BATCH   4096
#define NDIM    128
#define C_RAMP  0.5f
#define N_BLKS  500     // 500 * 8 = 4000 iterations max (matches reference)
#define BLK_IT  8
#define TOL     2e-4f   // prox-gradient residual (inf-norm) for early exit

#define PACK2(out, lo, hi) \
    asm("mov.b64 %0, {%1, %2};" : "=l"(out) : "r"(__float_as_uint(lo)), "r"(__float_as_uint(hi)))
#define UNPACK2(lo, hi, in) do {                                          \
    unsigned _ulo, _uhi;                                                  \
    asm("mov.b64 {%0, %1}, %2;" : "=r"(_ulo), "=r"(_uhi) : "l"(in));      \
    lo = __uint_as_float(_ulo); hi = __uint_as_float(_uhi); } while (0)
#define MUL2(out, a, b) \
    asm("mul.rn.f32x2 %0, %1, %2;" : "=l"(out) : "l"(a), "l"(b))
#define FMA2(out, a, b, c) \
    asm("fma.rn.f32x2 %0, %1, %2, %3;" : "=l"(out) : "l"(a), "l"(b), "l"(c))

__global__ __launch_bounds__(128)
void fista_warp_kernel(const float* __restrict__ z0,
                       const float* __restrict__ mu,
                       const float* __restrict__ dg,
                       const float* __restrict__ d2g,
                       float* __restrict__ out)
{
    const unsigned FULL = 0xffffffffu;
    int gwarp = (blockIdx.x * blockDim.x + threadIdx.x) >> 5;
    int lane  = threadIdx.x & 31;

    size_t vbase = (size_t)gwarp * (NDIM / 4) + lane;
    float4 z4 = ((const float4*)z0)[vbase];
    float4 m4v = ((const float4*)mu)[vbase];
    float4 g4 = ((const float4*)dg)[vbase];
    float4 h4 = ((const float4*)d2g)[vbase];

    // d = d2g + 1 ; p = dg - d2g*z0 - mu ; m = 1/d ; pn = -p*m  (pn = z(0))
    float d0 = h4.x + 1.0f, d1 = h4.y + 1.0f, d2 = h4.z + 1.0f, d3 = h4.w + 1.0f;
    float p0 = fmaf(-h4.x, z4.x, g4.x) - m4v.x;
    float p1 = fmaf(-h4.y, z4.y, g4.y) - m4v.y;
    float p2 = fmaf(-h4.z, z4.z, g4.z) - m4v.z;
    float p3 = fmaf(-h4.w, z4.w, g4.w) - m4v.w;
    float m0 = 1.0f / d0, m1 = 1.0f / d1, m2 = 1.0f / d2, m3 = 1.0f / d3;
    float pn0 = -p0 * m0, pn1 = -p1 * m1, pn2 = -p2 * m2, pn3 = -p3 * m3;

    // Right-neighbor constants (element 4l+4 of this item).
    float m4n = __shfl_down_sync(FULL, m0, 1);
    float pn4 = __shfl_down_sync(FULL, pn0, 1);

    // Jacobi-preconditioned steps: step_i = 0.5/(m_i + m_{i+1}).
    // Valid: A = D M D^T is diagonally dominant => A <= 2 diag(A).
    float step0 = 0.5f / (m0 + m1);
    float step1 = 0.5f / (m1 + m2);
    float step2 = 0.5f / (m2 + m3);
    float step3 = 0.5f / (m3 + m4n);

    // Stencil: x_i = 0.5*y_i + l_i*y_{i-1} + r_i*y_{i+1} + b_i
    float l0 = (lane == 0) ? 0.0f : step0 * m0;   // y_{-1} = 0 & kills garbage
    float l1 = step1 * m1;
    float l2 = step2 * m2;
    float l3 = step3 * m3;
    float r0 = step0 * m1;
    float r1 = step1 * m2;
    float r2 = step2 * m3;
    float r3 = step3 * m4n;
    float b0 = step0 * (pn0 - pn1);
    float b1 = step1 * (pn1 - pn2);
    float b2 = step2 * (pn2 - pn3);
    float b3 = step3 * (pn3 - pn4);

    // Per-element thresholds. Lane 31 elem 3 is the nonexistent dual index
    // 127: clamp(+/-MAX) forces n3 = x3 - x3 = 0 exactly, so y127 == 0
    // invariantly and its garbage coefficients never propagate.
    float thr0 = step0 * C_RAMP;
    float thr1 = step1 * C_RAMP;
    float thr2 = step2 * C_RAMP;
    float thr3 = (lane == 31) ? FLT_MAX : step3 * C_RAMP;

    float y0 = 0.f, y1 = 0.f, y2 = 0.f, y3 = 0.f;
    unsigned long long nu01 = 0ull, nu23 = 0ull;   // packed (nu0,nu1),(nu2,nu3)
    float ylm = 0.f, yrp = 0.f;     // y-halos: y[4l-1], y[4l+4]
    float nlmp = 0.f, nrpp = 0.f;   // previous n-halos (= nu halos)
    float kf = 0.f;                 // iterations since (re)start, as float

    const bool lane0 = (lane == 0);

    // One iteration; BETA block-constant; B12=(1+beta,1+beta), NB2=(-beta,-beta).
    // TRACK=true returns the prox-gradient residual RES = max_i |n_i - y_i|.
    #define FISTA_STEP(TRACK, RES, BETA, B12, NB2)                           \
    {                                                                        \
        float x0 = fmaf(0.5f, y0, b0);                                       \
        float x1 = fmaf(0.5f, y1, b1);                                       \
        float x2 = fmaf(0.5f, y2, b2);                                       \
        float x3 = fmaf(0.5f, y3, b3);                                       \
        x0 = fmaf(r0, y1, x0);                                               \
        x1 = fmaf(l1, y0, x1);  x1 = fmaf(r1, y2, x1);                       \
        x2 = fmaf(l2, y1, x2);  x2 = fmaf(r2, y3, x2);                       \
        x3 = fmaf(l3, y2, x3);                                               \
        x0 = fmaf(l0, ylm, x0);                                              \
        x3 = fmaf(r3, yrp, x3);                                              \
        /* soft threshold via clamp: n = x - clamp(x, -thr, thr) */          \
        float n0 = x0 - fminf(fmaxf(x0, -thr0), thr0);                       \
        float n1 = x1 - fminf(fmaxf(x1, -thr1), thr1);                       \
        float n2 = x2 - fminf(fmaxf(x2, -thr2), thr2);                       \
        float n3 = x3 - fminf(fmaxf(x3, -thr3), thr3);                       \
        /* n-halos: shuffles issue as soon as n0/n3 are ready */             \
        float nlm = __shfl_up_sync  (FULL, n3, 1);                           \
        float nrp = __shfl_down_sync(FULL, n0, 1);                           \
        if (TRACK) {                                                         \
            float r01 = fmaxf(fabsf(n0 - y0), fabsf(n1 - y1));               \
            float r23 = fmaxf(fabsf(n2 - y2), fabsf(n3 - y3));               \
            RES = fmaxf(r01, r23);                                           \
        }                                                                    \
        /* momentum: y = (1+beta)*n + (-beta)*nu  (packed f32x2) */          \
        unsigned long long n01, n23, t01, t23, yy01, yy23;                   \
        PACK2(n01, n0, n1);  PACK2(n23, n2, n3);                             \
        MUL2(t01, NB2, nu01);  MUL2(t23, NB2, nu23);                         \
        FMA2(yy01, B12, n01, t01);  FMA2(yy23, B12, n23, t23);               \
        nu01 = n01;  nu23 = n23;                                             \
        UNPACK2(y0, y1, yy01);  UNPACK2(y2, y3, yy23);                       \
        /* reconstruct y-halos locally (same beta as the neighbor used) */   \
        ylm = fmaf(BETA, nlm - nlmp, nlm);  nlmp = nlm;                      \
        yrp = fmaf(BETA, nrp - nrpp, nrp);  nrpp = nrp;                      \
    }

    float prev_res = FLT_MAX;

    for (int blk = 0; blk < N_BLKS; ++blk) {
        // block-constant beta = kf/(kf+3) at block-start kf (restart -> 0)
        float rk; asm("rcp.approx.f32 %0, %1;" : "=f"(rk) : "f"(kf + 3.0f));
        float beta  = kf * rk;
        float beta1 = 1.0f + beta;
        unsigned long long B12, NB2;
        PACK2(B12, beta1, beta1);
        PACK2(NB2, -beta, -beta);
        kf += (float)BLK_IT;

        float dres;
        #pragma unroll
        for (int j = 0; j < BLK_IT - 1; ++j)
            FISTA_STEP(false, dres, beta, B12, NB2)

        float res;
        FISTA_STEP(true, res, beta, B12, NB2)

        // warp-max of residual: res >= 0 so float bits are order-isomorphic
        float rmax = __uint_as_float(__reduce_max_sync(FULL, __float_as_uint(res)));
        if (rmax < TOL) break;

        // Residual-increase restart (warp-uniform). Halos need no shuffles:
        // y = nu everywhere, and the stored n-halos ARE the nu-halos.
        if (rmax > prev_res) {
            kf = 0.0f;
            UNPACK2(y0, y1, nu01);
            UNPACK2(y2, y3, nu23);
            ylm = nlmp;
            yrp = nrpp;
        }
        prev_res = rmax;
    }

    // z* from the FINAL nu: z_i = pn_i - m_i*(nu_i - nu_{i-1})
    float nu0, nu1, nu2, nu3;
    UNPACK2(nu0, nu1, nu01);
    UNPACK2(nu2, nu3, nu23);
    float num = __shfl_up_sync(FULL, nu3, 1);
    if (lane0) num = 0.0f;
    float4 o4;
    o4.x = fmaf(num - nu0, m0, pn0);
    o4.y = fmaf(nu0 - nu1, m1, pn1);
    o4.z = fmaf(nu1 - nu2, m2, pn2);
    o4.w = fmaf(nu2 - nu3, m3, pn3);
    ((float4*)out)[vbase] = o4;
}

extern "C" void kernel_launch(void* const* d_in, const int* in_sizes, int n_in,
                              void* d_out, int out_size)
{
    const float* z0  = (const float*)d_in[0];
    const float* mu  = (const float*)d_in[1];
    const float* dg  = (const float*)d_in[2];
    const float* d2g = (const float*)d_in[3];
    float* out = (float*)d_out;

    dim3 block(128);
    dim3 grid((BATCH * 32) / 128);   // 1024 blocks, 4 warps each
    fista_warp_kernel<<<grid, block>>>(z0, mu, dg, d2g, out);
}

// round 10
// speedup vs baseline: 1.0017x; 1.0017x over previous
#include <cuda_runtime.h>
#include <float.h>

// Batched Jacobi-preconditioned FISTA (+ residual-increase restart) on the
// dual of a ramp-constrained QP. One warp per batch item; 4 elements/lane,
// paired EVEN/ODD: packed lanes are (elem0,elem2) and (elem1,elem3), which
// makes the tridiagonal stencil's neighbor terms natural f32x2 operands
// (no swap-packs). Per-element Jacobi steps step_i = 0.5/(m_i + m_{i+1});
// diagonal stencil coefficient exactly 0.5. Halos exchange prox output n;
// y-halos reconstructed locally with block-constant beta.
#define BATCH   4096
#define NDIM    128
#define C_RAMP  0.5f
#define N_BLKS  500     // 500 * 8 = 4000 iterations max (matches reference)
#define BLK_IT  8
#define TOL     3e-4f   // prox-gradient residual (inf-norm) for early exit

#define PACK2(out, lo, hi) \
    asm("mov.b64 %0, {%1, %2};" : "=l"(out) : "r"(__float_as_uint(lo)), "r"(__float_as_uint(hi)))
#define UNPACK2(lo, hi, in) do {                                          \
    unsigned _ulo, _uhi;                                                  \
    asm("mov.b64 {%0, %1}, %2;" : "=r"(_ulo), "=r"(_uhi) : "l"(in));      \
    lo = __uint_as_float(_ulo); hi = __uint_as_float(_uhi); } while (0)
#define MUL2(out, a, b) \
    asm("mul.rn.f32x2 %0, %1, %2;" : "=l"(out) : "l"(a), "l"(b))
#define FMA2(out, a, b, c) \
    asm("fma.rn.f32x2 %0, %1, %2, %3;" : "=l"(out) : "l"(a), "l"(b), "l"(c))

__global__ __launch_bounds__(128)
void fista_warp_kernel(const float* __restrict__ z0,
                       const float* __restrict__ mu,
                       const float* __restrict__ dg,
                       const float* __restrict__ d2g,
                       float* __restrict__ out)
{
    const unsigned FULL = 0xffffffffu;
    int gwarp = (blockIdx.x * blockDim.x + threadIdx.x) >> 5;
    int lane  = threadIdx.x & 31;

    size_t vbase = (size_t)gwarp * (NDIM / 4) + lane;
    float4 z4 = ((const float4*)z0)[vbase];
    float4 m4v = ((const float4*)mu)[vbase];
    float4 g4 = ((const float4*)dg)[vbase];
    float4 h4 = ((const float4*)d2g)[vbase];

    // d = d2g + 1 ; p = dg - d2g*z0 - mu ; m = 1/d ; pn = -p*m  (pn = z(0))
    float d0 = h4.x + 1.0f, d1 = h4.y + 1.0f, d2 = h4.z + 1.0f, d3 = h4.w + 1.0f;
    float p0 = fmaf(-h4.x, z4.x, g4.x) - m4v.x;
    float p1 = fmaf(-h4.y, z4.y, g4.y) - m4v.y;
    float p2 = fmaf(-h4.z, z4.z, g4.z) - m4v.z;
    float p3 = fmaf(-h4.w, z4.w, g4.w) - m4v.w;
    float m0 = 1.0f / d0, m1 = 1.0f / d1, m2 = 1.0f / d2, m3 = 1.0f / d3;
    float pn0 = -p0 * m0, pn1 = -p1 * m1, pn2 = -p2 * m2, pn3 = -p3 * m3;

    // Right-neighbor constants (element 4l+4 of this item).
    float m4n = __shfl_down_sync(FULL, m0, 1);
    float pn4 = __shfl_down_sync(FULL, pn0, 1);

    // Jacobi-preconditioned steps: step_i = 0.5/(m_i + m_{i+1}).
    // Valid: A = D M D^T is diagonally dominant => A <= 2 diag(A).
    float step0 = 0.5f / (m0 + m1);
    float step1 = 0.5f / (m1 + m2);
    float step2 = 0.5f / (m2 + m3);
    float step3 = 0.5f / (m3 + m4n);

    // Stencil: x_i = 0.5*y_i + l_i*y_{i-1} + r_i*y_{i+1} + b_i
    float l0 = (lane == 0) ? 0.0f : step0 * m0;   // y_{-1} = 0 & kills garbage
    float l1 = step1 * m1;
    float l2 = step2 * m2;
    float l3 = step3 * m3;
    float r0 = step0 * m1;
    float r1 = step1 * m2;
    float r2 = step2 * m3;
    float r3 = step3 * m4n;
    float b0 = step0 * (pn0 - pn1);
    float b1 = step1 * (pn1 - pn2);
    float b2 = step2 * (pn2 - pn3);
    float b3 = step3 * (pn3 - pn4);

    // Packed stencil constants on even/odd pairs:
    //   xE=(x0,x2): 0.5*(y0,y2) + (r0,r2)*(y1,y3) + [scalar l0*ylm, l2*y1] + (b0,b2)
    //   xO=(x1,x3): 0.5*(y1,y3) + (l1,l3)*(y0,y2) + [scalar r1*y2, r3*yrp] + (b1,b3)
    unsigned long long H2, B02, B13, R02, L13;
    PACK2(H2,  0.5f, 0.5f);
    PACK2(B02, b0, b2);
    PACK2(B13, b1, b3);
    PACK2(R02, r0, r2);
    PACK2(L13, l1, l3);

    // Per-element thresholds. Lane 31 elem 3 is the nonexistent dual index
    // 127: clamp(+/-MAX) forces n3 = x3 - x3 = 0 exactly, so y127 == 0
    // invariantly and its garbage coefficients never propagate.
    float thr0 = step0 * C_RAMP;
    float thr1 = step1 * C_RAMP;
    float thr2 = step2 * C_RAMP;
    float thr3 = (lane == 31) ? FLT_MAX : step3 * C_RAMP;

    // State: packed even/odd y and nu, plus scalar views of y.
    unsigned long long yyE = 0ull, yyO = 0ull;     // (y0,y2), (y1,y3)
    unsigned long long nuE = 0ull, nuO = 0ull;     // (nu0,nu2), (nu1,nu3)
    float y0 = 0.f, y1 = 0.f, y2 = 0.f, y3 = 0.f;
    float ylm = 0.f, yrp = 0.f;     // y-halos: y[4l-1], y[4l+4]
    float nlmp = 0.f, nrpp = 0.f;   // previous n-halos (= nu halos)
    float kf = 0.f;                 // iterations since (re)start, as float

    const bool lane0 = (lane == 0);

    // One iteration; BETA block-constant; B12=(1+beta,..), NB2=(-beta,..).
    // TRACK=true returns the prox-gradient residual RES = max_i |n_i - y_i|.
    #define FISTA_STEP(TRACK, RES, BETA, B12, NB2)                           \
    {                                                                        \
        unsigned long long xE, xO;                                           \
        FMA2(xE, H2, yyE, B02);                                              \
        FMA2(xE, R02, yyO, xE);                                              \
        FMA2(xO, H2, yyO, B13);                                              \
        FMA2(xO, L13, yyE, xO);                                              \
        float x0, x1, x2, x3;                                                \
        UNPACK2(x0, x2, xE);                                                 \
        UNPACK2(x1, x3, xO);                                                 \
        x0 = fmaf(l0, ylm, x0);                                              \
        x2 = fmaf(l2, y1,  x2);                                              \
        x1 = fmaf(r1, y2,  x1);                                              \
        x3 = fmaf(r3, yrp, x3);                                              \
        /* soft threshold via clamp: n = x - clamp(x, -thr, thr) */          \
        float n0 = x0 - fminf(fmaxf(x0, -thr0), thr0);                       \
        float n1 = x1 - fminf(fmaxf(x1, -thr1), thr1);                       \
        float n2 = x2 - fminf(fmaxf(x2, -thr2), thr2);                       \
        float n3 = x3 - fminf(fmaxf(x3, -thr3), thr3);                       \
        /* n-halos: shuffles issue as soon as n0/n3 are ready */             \
        float nlm = __shfl_up_sync  (FULL, n3, 1);                           \
        float nrp = __shfl_down_sync(FULL, n0, 1);                           \
        if (TRACK) {                                                         \
            float r01 = fmaxf(fabsf(n0 - y0), fabsf(n1 - y1));               \
            float r23 = fmaxf(fabsf(n2 - y2), fabsf(n3 - y3));               \
            RES = fmaxf(r01, r23);                                           \
        }                                                                    \
        /* momentum: y = (1+beta)*n + (-beta)*nu  (packed f32x2) */          \
        unsigned long long nE, nO, tE, tO;                                   \
        PACK2(nE, n0, n2);  PACK2(nO, n1, n3);                               \
        MUL2(tE, NB2, nuE);  MUL2(tO, NB2, nuO);                             \
        FMA2(yyE, B12, nE, tE);  FMA2(yyO, B12, nO, tO);                     \
        nuE = nE;  nuO = nO;                                                 \
        UNPACK2(y0, y2, yyE);  UNPACK2(y1, y3, yyO);                         \
        /* reconstruct y-halos locally (same beta as the neighbor used) */   \
        ylm = fmaf(BETA, nlm - nlmp, nlm);  nlmp = nlm;                      \
        yrp = fmaf(BETA, nrp - nrpp, nrp);  nrpp = nrp;                      \
    }

    float prev_res = FLT_MAX;

    for (int blk = 0; blk < N_BLKS; ++blk) {
        // block-constant beta = kf/(kf+3) at block-start kf (restart -> 0)
        float rk; asm("rcp.approx.f32 %0, %1;" : "=f"(rk) : "f"(kf + 3.0f));
        float beta  = kf * rk;
        float beta1 = 1.0f + beta;
        unsigned long long B12, NB2;
        PACK2(B12, beta1, beta1);
        PACK2(NB2, -beta, -beta);
        kf += (float)BLK_IT;

        float dres;
        #pragma unroll
        for (int j = 0; j < BLK_IT - 1; ++j)
            FISTA_STEP(false, dres, beta, B12, NB2)

        float res;
        FISTA_STEP(true, res, beta, B12, NB2)

        // warp-max of residual: res >= 0 so float bits are order-isomorphic
        float rmax = __uint_as_float(__reduce_max_sync(FULL, __float_as_uint(res)));
        if (rmax < TOL) break;

        // Residual-increase restart (warp-uniform). Halos need no shuffles:
        // y = nu everywhere, and the stored n-halos ARE the nu-halos.
        if (rmax > prev_res) {
            kf = 0.0f;
            yyE = nuE;  yyO = nuO;
            UNPACK2(y0, y2, yyE);
            UNPACK2(y1, y3, yyO);
            ylm = nlmp;
            yrp = nrpp;
        }
        prev_res = rmax;
    }

    // z* from the FINAL nu: z_i = pn_i - m_i*(nu_i - nu_{i-1})
    float nu0, nu1, nu2, nu3;
    UNPACK2(nu0, nu2, nuE);
    UNPACK2(nu1, nu3, nuO);
    float num = __shfl_up_sync(FULL, nu3, 1);
    if (lane0) num = 0.0f;
    float4 o4;
    o4.x = fmaf(num - nu0, m0, pn0);
    o4.y = fmaf(nu0 - nu1, m1, pn1);
    o4.z = fmaf(nu1 - nu2, m2, pn2);
    o4.w = fmaf(nu2 - nu3, m3, pn3);
    ((float4*)out)[vbase] = o4;
}

extern "C" void kernel_launch(void* const* d_in, const int* in_sizes, int n_in,
                              void* d_out, int out_size)
{
    const float* z0  = (const float*)d_in[0];
    const float* mu  = (const float*)d_in[1];
    const float* dg  = (const float*)d_in[2];
    const float* d2g = (const float*)d_in[3];
    float* out = (float*)d_out;

    dim3 block(128);
    dim3 grid((BATCH * 32) / 128);   // 1024 blocks, 4 warps each
    fista_warp_kernel<<<grid, block>>>(z0, mu, dg, d2g, out);
}

// round 11
// speedup vs baseline: 1.0101x; 1.0084x over previous
#include <cuda_runtime.h>
#include <float.h>

// Batched Jacobi-preconditioned FISTA (+ residual-increase restart) on the
// dual of a ramp-constrained QP. One warp per batch item; 4 elements/lane,
// paired EVEN/ODD for natural f32x2 stencil operands. Per-element Jacobi
// steps step_i = 0.5/(m_i + m_{i+1}); diagonal stencil coeff exactly 0.5.
// Halos exchange prox output n; y-halos reconstructed with block-constant
// beta. Momentum ramp beta_k = k/(k+2) (fast ramp; restart-guarded).
#define BATCH   4096
#define NDIM    128
#define C_RAMP  0.5f
#define N_BLKS  500     // 500 * 8 = 4000 iterations max (matches reference)
#define BLK_IT  8
#define TOL     4e-4f   // prox-gradient residual (inf-norm) for early exit

#define PACK2(out, lo, hi) \
    asm("mov.b64 %0, {%1, %2};" : "=l"(out) : "r"(__float_as_uint(lo)), "r"(__float_as_uint(hi)))
#define UNPACK2(lo, hi, in) do {                                          \
    unsigned _ulo, _uhi;                                                  \
    asm("mov.b64 {%0, %1}, %2;" : "=r"(_ulo), "=r"(_uhi) : "l"(in));      \
    lo = __uint_as_float(_ulo); hi = __uint_as_float(_uhi); } while (0)
#define MUL2(out, a, b) \
    asm("mul.rn.f32x2 %0, %1, %2;" : "=l"(out) : "l"(a), "l"(b))
#define FMA2(out, a, b, c) \
    asm("fma.rn.f32x2 %0, %1, %2, %3;" : "=l"(out) : "l"(a), "l"(b), "l"(c))

__global__ __launch_bounds__(128)
void fista_warp_kernel(const float* __restrict__ z0,
                       const float* __restrict__ mu,
                       const float* __restrict__ dg,
                       const float* __restrict__ d2g,
                       float* __restrict__ out)
{
    const unsigned FULL = 0xffffffffu;
    int gwarp = (blockIdx.x * blockDim.x + threadIdx.x) >> 5;
    int lane  = threadIdx.x & 31;

    size_t vbase = (size_t)gwarp * (NDIM / 4) + lane;
    float4 z4 = ((const float4*)z0)[vbase];
    float4 m4v = ((const float4*)mu)[vbase];
    float4 g4 = ((const float4*)dg)[vbase];
    float4 h4 = ((const float4*)d2g)[vbase];

    // d = d2g + 1 ; p = dg - d2g*z0 - mu ; m = 1/d ; pn = -p*m  (pn = z(0))
    float d0 = h4.x + 1.0f, d1 = h4.y + 1.0f, d2 = h4.z + 1.0f, d3 = h4.w + 1.0f;
    float p0 = fmaf(-h4.x, z4.x, g4.x) - m4v.x;
    float p1 = fmaf(-h4.y, z4.y, g4.y) - m4v.y;
    float p2 = fmaf(-h4.z, z4.z, g4.z) - m4v.z;
    float p3 = fmaf(-h4.w, z4.w, g4.w) - m4v.w;
    float m0 = 1.0f / d0, m1 = 1.0f / d1, m2 = 1.0f / d2, m3 = 1.0f / d3;
    float pn0 = -p0 * m0, pn1 = -p1 * m1, pn2 = -p2 * m2, pn3 = -p3 * m3;

    // Right-neighbor constants (element 4l+4 of this item).
    float m4n = __shfl_down_sync(FULL, m0, 1);
    float pn4 = __shfl_down_sync(FULL, pn0, 1);

    // Jacobi-preconditioned steps: step_i = 0.5/(m_i + m_{i+1}).
    // Valid: A = D M D^T is diagonally dominant => A <= 2 diag(A).
    float step0 = 0.5f / (m0 + m1);
    float step1 = 0.5f / (m1 + m2);
    float step2 = 0.5f / (m2 + m3);
    float step3 = 0.5f / (m3 + m4n);

    // Stencil: x_i = 0.5*y_i + l_i*y_{i-1} + r_i*y_{i+1} + b_i
    float l0 = (lane == 0) ? 0.0f : step0 * m0;   // y_{-1} = 0 & kills garbage
    float l1 = step1 * m1;
    float l2 = step2 * m2;
    float l3 = step3 * m3;
    float r0 = step0 * m1;
    float r1 = step1 * m2;
    float r2 = step2 * m3;
    float r3 = step3 * m4n;
    float b0 = step0 * (pn0 - pn1);
    float b1 = step1 * (pn1 - pn2);
    float b2 = step2 * (pn2 - pn3);
    float b3 = step3 * (pn3 - pn4);

    // Packed stencil constants on even/odd pairs:
    //   xE=(x0,x2): 0.5*(y0,y2) + (r0,r2)*(y1,y3) + [scalar l0*ylm, l2*y1] + (b0,b2)
    //   xO=(x1,x3): 0.5*(y1,y3) + (l1,l3)*(y0,y2) + [scalar r1*y2, r3*yrp] + (b1,b3)
    unsigned long long H2, B02, B13, R02, L13;
    PACK2(H2,  0.5f, 0.5f);
    PACK2(B02, b0, b2);
    PACK2(B13, b1, b3);
    PACK2(R02, r0, r2);
    PACK2(L13, l1, l3);

    // Per-element thresholds. Lane 31 elem 3 is the nonexistent dual index
    // 127: clamp(+/-MAX) forces n3 = x3 - x3 = 0 exactly, so y127 == 0
    // invariantly and its garbage coefficients never propagate.
    float thr0 = step0 * C_RAMP;
    float thr1 = step1 * C_RAMP;
    float thr2 = step2 * C_RAMP;
    float thr3 = (lane == 31) ? FLT_MAX : step3 * C_RAMP;

    // State: packed even/odd y and nu, plus scalar views of y.
    unsigned long long yyE = 0ull, yyO = 0ull;     // (y0,y2), (y1,y3)
    unsigned long long nuE = 0ull, nuO = 0ull;     // (nu0,nu2), (nu1,nu3)
    float y0 = 0.f, y1 = 0.f, y2 = 0.f, y3 = 0.f;
    float ylm = 0.f, yrp = 0.f;     // y-halos: y[4l-1], y[4l+4]
    float nlmp = 0.f, nrpp = 0.f;   // previous n-halos (= nu halos)
    float kf = 0.f;                 // iterations since (re)start, as float

    const bool lane0 = (lane == 0);

    // One iteration; BETA block-constant; B12=(1+beta,..), NB2=(-beta,..).
    // TRACK=true returns the prox-gradient residual RES = max_i |n_i - y_i|.
    #define FISTA_STEP(TRACK, RES, BETA, B12, NB2)                           \
    {                                                                        \
        unsigned long long xE, xO;                                           \
        FMA2(xE, H2, yyE, B02);                                              \
        FMA2(xE, R02, yyO, xE);                                              \
        FMA2(xO, H2, yyO, B13);                                              \
        FMA2(xO, L13, yyE, xO);                                              \
        float x0, x1, x2, x3;                                                \
        UNPACK2(x0, x2, xE);                                                 \
        UNPACK2(x1, x3, xO);                                                 \
        x0 = fmaf(l0, ylm, x0);                                              \
        x2 = fmaf(l2, y1,  x2);                                              \
        x1 = fmaf(r1, y2,  x1);                                              \
        x3 = fmaf(r3, yrp, x3);                                              \
        /* soft threshold via clamp: n = x - clamp(x, -thr, thr) */          \
        float n0 = x0 - fminf(fmaxf(x0, -thr0), thr0);                       \
        float n1 = x1 - fminf(fmaxf(x1, -thr1), thr1);                       \
        float n2 = x2 - fminf(fmaxf(x2, -thr2), thr2);                       \
        float n3 = x3 - fminf(fmaxf(x3, -thr3), thr3);                       \
        /* n-halos: shuffles issue as soon as n0/n3 are ready */             \
        float nlm = __shfl_up_sync  (FULL, n3, 1);                           \
        float nrp = __shfl_down_sync(FULL, n0, 1);                           \
        if (TRACK) {                                                         \
            float r01 = fmaxf(fabsf(n0 - y0), fabsf(n1 - y1));               \
            float r23 = fmaxf(fabsf(n2 - y2), fabsf(n3 - y3));               \
            RES = fmaxf(r01, r23);                                           \
        }                                                                    \
        /* momentum: y = (1+beta)*n + (-beta)*nu  (packed f32x2) */          \
        unsigned long long nE, nO, tE, tO;                                   \
        PACK2(nE, n0, n2);  PACK2(nO, n1, n3);                               \
        MUL2(tE, NB2, nuE);  MUL2(tO, NB2, nuO);                             \
        FMA2(yyE, B12, nE, tE);  FMA2(yyO, B12, nO, tO);                     \
        nuE = nE;  nuO = nO;                                                 \
        UNPACK2(y0, y2, yyE);  UNPACK2(y1, y3, yyO);                         \
        /* reconstruct y-halos locally (same beta as the neighbor used) */   \
        ylm = fmaf(BETA, nlm - nlmp, nlm);  nlmp = nlm;                      \
        yrp = fmaf(BETA, nrp - nrpp, nrp);  nrpp = nrp;                      \
    }

    float prev_res = FLT_MAX;

    for (int blk = 0; blk < N_BLKS; ++blk) {
        // block-constant beta = kf/(kf+2) at block-start kf (restart -> 0):
        // fastest admissible FISTA ramp (a=2), restart-guarded.
        float rk; asm("rcp.approx.f32 %0, %1;" : "=f"(rk) : "f"(kf + 2.0f));
        float beta  = kf * rk;
        float beta1 = 1.0f + beta;
        unsigned long long B12, NB2;
        PACK2(B12, beta1, beta1);
        PACK2(NB2, -beta, -beta);
        kf += (float)BLK_IT;

        float dres;
        #pragma unroll
        for (int j = 0; j < BLK_IT - 1; ++j)
            FISTA_STEP(false, dres, beta, B12, NB2)

        float res;
        FISTA_STEP(true, res, beta, B12, NB2)

        // warp-max of residual: res >= 0 so float bits are order-isomorphic
        float rmax = __uint_as_float(__reduce_max_sync(FULL, __float_as_uint(res)));
        if (rmax < TOL) break;

        // Residual-increase restart (warp-uniform). Halos need no shuffles:
        // y = nu everywhere, and the stored n-halos ARE the nu-halos.
        if (rmax > prev_res) {
            kf = 0.0f;
            yyE = nuE;  yyO = nuO;
            UNPACK2(y0, y2, yyE);
            UNPACK2(y1, y3, yyO);
            ylm = nlmp;
            yrp = nrpp;
        }
        prev_res = rmax;
    }

    // z* from the FINAL nu: z_i = pn_i - m_i*(nu_i - nu_{i-1})
    float nu0, nu1, nu2, nu3;
    UNPACK2(nu0, nu2, nuE);
    UNPACK2(nu1, nu3, nuO);
    float num = __shfl_up_sync(FULL, nu3, 1);
    if (lane0) num = 0.0f;
    float4 o4;
    o4.x = fmaf(num - nu0, m0, pn0);
    o4.y = fmaf(nu0 - nu1, m1, pn1);
    o4.z = fmaf(nu1 - nu2, m2, pn2);
    o4.w = fmaf(nu2 - nu3, m3, pn3);
    ((float4*)out)[vbase] = o4;
}

extern "C" void kernel_launch(void* const* d_in, const int* in_sizes, int n_in,
                              void* d_out, int out_size)
{
    const float* z0  = (const float*)d_in[0];
    const float* mu  = (const float*)d_in[1];
    const float* dg  = (const float*)d_in[2];
    const float* d2g = (const float*)d_in[3];
    float* out = (float*)d_out;

    dim3 block(128);
    dim3 grid((BATCH * 32) / 128);   // 1024 blocks, 4 warps each
    fista_warp_kernel<<<grid, block>>>(z0, mu, dg, d2g, out);
}

// round 12
// speedup vs baseline: 1.1304x; 1.1191x over previous
#include <cuda_runtime.h>
#include <float.h>

// Batched Jacobi-preconditioned FISTA (+ residual-increase restart) on the
// dual of a ramp-constrained QP. One warp per batch item; 4 elements/lane,
// paired EVEN/ODD for natural f32x2 stencil operands. Per-element Jacobi
// steps step_i = 0.5/(m_i + m_{i+1}); diagonal stencil coeff exactly 0.5.
// Halos exchange prox output n; y-halos reconstructed with block-constant
// beta. Momentum ramp beta_k = k/(k+3) (measured-best; restart-guarded).
#define BATCH   4096
#define NDIM    128
#define C_RAMP  0.5f
#define N_BLKS  500     // 500 * 8 = 4000 iterations max (matches reference)
#define BLK_IT  8
#define TOL     4.5e-4f // prox-gradient residual (inf-norm) for early exit

#define PACK2(out, lo, hi) \
    asm("mov.b64 %0, {%1, %2};" : "=l"(out) : "r"(__float_as_uint(lo)), "r"(__float_as_uint(hi)))
#define UNPACK2(lo, hi, in) do {                                          \
    unsigned _ulo, _uhi;                                                  \
    asm("mov.b64 {%0, %1}, %2;" : "=r"(_ulo), "=r"(_uhi) : "l"(in));      \
    lo = __uint_as_float(_ulo); hi = __uint_as_float(_uhi); } while (0)
#define MUL2(out, a, b) \
    asm("mul.rn.f32x2 %0, %1, %2;" : "=l"(out) : "l"(a), "l"(b))
#define FMA2(out, a, b, c) \
    asm("fma.rn.f32x2 %0, %1, %2, %3;" : "=l"(out) : "l"(a), "l"(b), "l"(c))

__global__ __launch_bounds__(128)
void fista_warp_kernel(const float* __restrict__ z0,
                       const float* __restrict__ mu,
                       const float* __restrict__ dg,
                       const float* __restrict__ d2g,
                       float* __restrict__ out)
{
    const unsigned FULL = 0xffffffffu;
    int gwarp = (blockIdx.x * blockDim.x + threadIdx.x) >> 5;
    int lane  = threadIdx.x & 31;

    size_t vbase = (size_t)gwarp * (NDIM / 4) + lane;
    float4 z4 = ((const float4*)z0)[vbase];
    float4 m4v = ((const float4*)mu)[vbase];
    float4 g4 = ((const float4*)dg)[vbase];
    float4 h4 = ((const float4*)d2g)[vbase];

    // d = d2g + 1 ; p = dg - d2g*z0 - mu ; m = 1/d ; pn = -p*m  (pn = z(0))
    float d0 = h4.x + 1.0f, d1 = h4.y + 1.0f, d2 = h4.z + 1.0f, d3 = h4.w + 1.0f;
    float p0 = fmaf(-h4.x, z4.x, g4.x) - m4v.x;
    float p1 = fmaf(-h4.y, z4.y, g4.y) - m4v.y;
    float p2 = fmaf(-h4.z, z4.z, g4.z) - m4v.z;
    float p3 = fmaf(-h4.w, z4.w, g4.w) - m4v.w;
    float m0 = 1.0f / d0, m1 = 1.0f / d1, m2 = 1.0f / d2, m3 = 1.0f / d3;
    float pn0 = -p0 * m0, pn1 = -p1 * m1, pn2 = -p2 * m2, pn3 = -p3 * m3;

    // Right-neighbor constants (element 4l+4 of this item).
    float m4n = __shfl_down_sync(FULL, m0, 1);
    float pn4 = __shfl_down_sync(FULL, pn0, 1);

    // Jacobi-preconditioned steps: step_i = 0.5/(m_i + m_{i+1}).
    // Valid: A = D M D^T is diagonally dominant => A <= 2 diag(A).
    float step0 = 0.5f / (m0 + m1);
    float step1 = 0.5f / (m1 + m2);
    float step2 = 0.5f / (m2 + m3);
    float step3 = 0.5f / (m3 + m4n);

    // Stencil: x_i = 0.5*y_i + l_i*y_{i-1} + r_i*y_{i+1} + b_i
    float l0 = (lane == 0) ? 0.0f : step0 * m0;   // y_{-1} = 0 & kills garbage
    float l1 = step1 * m1;
    float l2 = step2 * m2;
    float l3 = step3 * m3;
    float r0 = step0 * m1;
    float r1 = step1 * m2;
    float r2 = step2 * m3;
    float r3 = step3 * m4n;
    float b0 = step0 * (pn0 - pn1);
    float b1 = step1 * (pn1 - pn2);
    float b2 = step2 * (pn2 - pn3);
    float b3 = step3 * (pn3 - pn4);

    // Packed stencil constants on even/odd pairs:
    //   xE=(x0,x2): 0.5*(y0,y2) + (r0,r2)*(y1,y3) + [scalar l0*ylm, l2*y1] + (b0,b2)
    //   xO=(x1,x3): 0.5*(y1,y3) + (l1,l3)*(y0,y2) + [scalar r1*y2, r3*yrp] + (b1,b3)
    unsigned long long H2, B02, B13, R02, L13;
    PACK2(H2,  0.5f, 0.5f);
    PACK2(B02, b0, b2);
    PACK2(B13, b1, b3);
    PACK2(R02, r0, r2);
    PACK2(L13, l1, l3);

    // Per-element thresholds. Lane 31 elem 3 is the nonexistent dual index
    // 127: clamp(+/-MAX) forces n3 = x3 - x3 = 0 exactly, so y127 == 0
    // invariantly and its garbage coefficients never propagate.
    float thr0 = step0 * C_RAMP;
    float thr1 = step1 * C_RAMP;
    float thr2 = step2 * C_RAMP;
    float thr3 = (lane == 31) ? FLT_MAX : step3 * C_RAMP;

    // State: packed even/odd y and nu, plus scalar views of y.
    unsigned long long yyE = 0ull, yyO = 0ull;     // (y0,y2), (y1,y3)
    unsigned long long nuE = 0ull, nuO = 0ull;     // (nu0,nu2), (nu1,nu3)
    float y0 = 0.f, y1 = 0.f, y2 = 0.f, y3 = 0.f;
    float ylm = 0.f, yrp = 0.f;     // y-halos: y[4l-1], y[4l+4]
    float nlmp = 0.f, nrpp = 0.f;   // previous n-halos (= nu halos)
    float kf = 0.f;                 // iterations since (re)start, as float

    const bool lane0 = (lane == 0);

    // One iteration; BETA block-constant; B12=(1+beta,..), NB2=(-beta,..).
    // TRACK=true returns the prox-gradient residual RES = max_i |n_i - y_i|.
    #define FISTA_STEP(TRACK, RES, BETA, B12, NB2)                           \
    {                                                                        \
        unsigned long long xE, xO;                                           \
        FMA2(xE, H2, yyE, B02);                                              \
        FMA2(xE, R02, yyO, xE);                                              \
        FMA2(xO, H2, yyO, B13);                                              \
        FMA2(xO, L13, yyE, xO);                                              \
        float x0, x1, x2, x3;                                                \
        UNPACK2(x0, x2, xE);                                                 \
        UNPACK2(x1, x3, xO);                                                 \
        x0 = fmaf(l0, ylm, x0);                                              \
        x2 = fmaf(l2, y1,  x2);                                              \
        x1 = fmaf(r1, y2,  x1);                                              \
        x3 = fmaf(r3, yrp, x3);                                              \
        /* soft threshold via clamp: n = x - clamp(x, -thr, thr) */          \
        float n0 = x0 - fminf(fmaxf(x0, -thr0), thr0);                       \
        float n1 = x1 - fminf(fmaxf(x1, -thr1), thr1);                       \
        float n2 = x2 - fminf(fmaxf(x2, -thr2), thr2);                       \
        float n3 = x3 - fminf(fmaxf(x3, -thr3), thr3);                       \
        /* n-halos: shuffles issue as soon as n0/n3 are ready */             \
        float nlm = __shfl_up_sync  (FULL, n3, 1);                           \
        float nrp = __shfl_down_sync(FULL, n0, 1);                           \
        if (TRACK) {                                                         \
            float r01 = fmaxf(fabsf(n0 - y0), fabsf(n1 - y1));               \
            float r23 = fmaxf(fabsf(n2 - y2), fabsf(n3 - y3));               \
            RES = fmaxf(r01, r23);                                           \
        }                                                                    \
        /* momentum: y = (1+beta)*n + (-beta)*nu  (packed f32x2) */          \
        unsigned long long nE, nO, tE, tO;                                   \
        PACK2(nE, n0, n2);  PACK2(nO, n1, n3);                               \
        MUL2(tE, NB2, nuE);  MUL2(tO, NB2, nuO);                             \
        FMA2(yyE, B12, nE, tE);  FMA2(yyO, B12, nO, tO);                     \
        nuE = nE;  nuO = nO;                                                 \
        UNPACK2(y0, y2, yyE);  UNPACK2(y1, y3, yyO);                         \
        /* reconstruct y-halos locally (same beta as the neighbor used) */   \
        ylm = fmaf(BETA, nlm - nlmp, nlm);  nlmp = nlm;                      \
        yrp = fmaf(BETA, nrp - nrpp, nrp);  nrpp = nrp;                      \
    }

    float prev_res = FLT_MAX;

    for (int blk = 0; blk < N_BLKS; ++blk) {
        // block-constant beta = kf/(kf+3) at block-start kf (restart -> 0)
        float rk; asm("rcp.approx.f32 %0, %1;" : "=f"(rk) : "f"(kf + 3.0f));
        float beta  = kf * rk;
        float beta1 = 1.0f + beta;
        unsigned long long B12, NB2;
        PACK2(B12, beta1, beta1);
        PACK2(NB2, -beta, -beta);
        kf += (float)BLK_IT;

        float dres;
        #pragma unroll
        for (int j = 0; j < BLK_IT - 1; ++j)
            FISTA_STEP(false, dres, beta, B12, NB2)

        float res;
        FISTA_STEP(true, res, beta, B12, NB2)

        // warp-max of residual: res >= 0 so float bits are order-isomorphic
        float rmax = __uint_as_float(__reduce_max_sync(FULL, __float_as_uint(res)));
        if (rmax < TOL) break;

        // Residual-increase restart (warp-uniform). Halos need no shuffles:
        // y = nu everywhere, and the stored n-halos ARE the nu-halos.
        if (rmax > prev_res) {
            kf = 0.0f;
            yyE = nuE;  yyO = nuO;
            UNPACK2(y0, y2, yyE);
            UNPACK2(y1, y3, yyO);
            ylm = nlmp;
            yrp = nrpp;
        }
        prev_res = rmax;
    }

    // z* from the FINAL nu: z_i = pn_i - m_i*(nu_i - nu_{i-1})
    float nu0, nu1, nu2, nu3;
    UNPACK2(nu0, nu2, nuE);
    UNPACK2(nu1, nu3, nuO);
    float num = __shfl_up_sync(FULL, nu3, 1);
    if (lane0) num = 0.0f;
    float4 o4;
    o4.x = fmaf(num - nu0, m0, pn0);
    o4.y = fmaf(nu0 - nu1, m1, pn1);
    o4.z = fmaf(nu1 - nu2, m2, pn2);
    o4.w = fmaf(nu2 - nu3, m3, pn3);
    ((float4*)out)[vbase] = o4;
}

extern "C" void kernel_launch(void* const* d_in, const int* in_sizes, int n_in,
                              void* d_out, int out_size)
{
    const float* z0  = (const float*)d_in[0];
    const float* mu  = (const float*)d_in[1];
    const float* dg  = (const float*)d_in[2];
    const float* d2g = (const float*)d_in[3];
    float* out = (float*)d_out;

    dim3 block(128);
    dim3 grid((BATCH * 32) / 128);   // 1024 blocks, 4 warps each
    fista_warp_kernel<<<grid, block>>>(z0, mu, dg, d2g, out);
}

// round 13
// speedup vs baseline: 1.2696x; 1.1231x over previous
#include <cuda_runtime.h>
#include <float.h>

// Batched Jacobi-preconditioned FISTA (+ residual-increase restart) on the
// dual of a ramp-constrained QP. One warp per batch item; 4 elements/lane,
// paired EVEN/ODD for natural f32x2 stencil operands. Per-element Jacobi
// steps step_i = 0.5/(m_i + m_{i+1}); diagonal stencil coeff exactly 0.5.
// y-halos shuffled directly at end of iteration (shortest cross-lane cycle:
// mom FMA2 -> SHFL -> inject FMA -> clamp). Momentum ramp beta_k = k/(k+3).
#define BATCH   4096
#define NDIM    128
#define C_RAMP  0.5f
#define N_BLKS  500     // 500 * 8 = 4000 iterations max (matches reference)
#define BLK_IT  8
#define TOL     5e-4f   // prox-gradient residual (inf-norm) for early exit

#define PACK2(out, lo, hi) \
    asm("mov.b64 %0, {%1, %2};" : "=l"(out) : "r"(__float_as_uint(lo)), "r"(__float_as_uint(hi)))
#define UNPACK2(lo, hi, in) do {                                          \
    unsigned _ulo, _uhi;                                                  \
    asm("mov.b64 {%0, %1}, %2;" : "=r"(_ulo), "=r"(_uhi) : "l"(in));      \
    lo = __uint_as_float(_ulo); hi = __uint_as_float(_uhi); } while (0)
#define MUL2(out, a, b) \
    asm("mul.rn.f32x2 %0, %1, %2;" : "=l"(out) : "l"(a), "l"(b))
#define FMA2(out, a, b, c) \
    asm("fma.rn.f32x2 %0, %1, %2, %3;" : "=l"(out) : "l"(a), "l"(b), "l"(c))

__global__ __launch_bounds__(128)
void fista_warp_kernel(const float* __restrict__ z0,
                       const float* __restrict__ mu,
                       const float* __restrict__ dg,
                       const float* __restrict__ d2g,
                       float* __restrict__ out)
{
    const unsigned FULL = 0xffffffffu;
    int gwarp = (blockIdx.x * blockDim.x + threadIdx.x) >> 5;
    int lane  = threadIdx.x & 31;

    size_t vbase = (size_t)gwarp * (NDIM / 4) + lane;
    float4 z4 = ((const float4*)z0)[vbase];
    float4 m4v = ((const float4*)mu)[vbase];
    float4 g4 = ((const float4*)dg)[vbase];
    float4 h4 = ((const float4*)d2g)[vbase];

    // d = d2g + 1 ; p = dg - d2g*z0 - mu ; m = 1/d ; pn = -p*m  (pn = z(0))
    float d0 = h4.x + 1.0f, d1 = h4.y + 1.0f, d2 = h4.z + 1.0f, d3 = h4.w + 1.0f;
    float p0 = fmaf(-h4.x, z4.x, g4.x) - m4v.x;
    float p1 = fmaf(-h4.y, z4.y, g4.y) - m4v.y;
    float p2 = fmaf(-h4.z, z4.z, g4.z) - m4v.z;
    float p3 = fmaf(-h4.w, z4.w, g4.w) - m4v.w;
    float m0 = 1.0f / d0, m1 = 1.0f / d1, m2 = 1.0f / d2, m3 = 1.0f / d3;
    float pn0 = -p0 * m0, pn1 = -p1 * m1, pn2 = -p2 * m2, pn3 = -p3 * m3;

    // Right-neighbor constants (element 4l+4 of this item).
    float m4n = __shfl_down_sync(FULL, m0, 1);
    float pn4 = __shfl_down_sync(FULL, pn0, 1);

    // Jacobi-preconditioned steps: step_i = 0.5/(m_i + m_{i+1}).
    // Valid: A = D M D^T is diagonally dominant => A <= 2 diag(A).
    float step0 = 0.5f / (m0 + m1);
    float step1 = 0.5f / (m1 + m2);
    float step2 = 0.5f / (m2 + m3);
    float step3 = 0.5f / (m3 + m4n);

    // Stencil: x_i = 0.5*y_i + l_i*y_{i-1} + r_i*y_{i+1} + b_i
    float l0 = (lane == 0) ? 0.0f : step0 * m0;   // y_{-1} = 0 & kills garbage
    float l1 = step1 * m1;
    float l2 = step2 * m2;
    float l3 = step3 * m3;
    float r0 = step0 * m1;
    float r1 = step1 * m2;
    float r2 = step2 * m3;
    float r3 = step3 * m4n;
    float b0 = step0 * (pn0 - pn1);
    float b1 = step1 * (pn1 - pn2);
    float b2 = step2 * (pn2 - pn3);
    float b3 = step3 * (pn3 - pn4);

    // Packed stencil constants on even/odd pairs:
    //   xE=(x0,x2): 0.5*(y0,y2) + (r0,r2)*(y1,y3) + [scalar l0*ylm, l2*y1] + (b0,b2)
    //   xO=(x1,x3): 0.5*(y1,y3) + (l1,l3)*(y0,y2) + [scalar r1*y2, r3*yrp] + (b1,b3)
    unsigned long long H2, B02, B13, R02, L13;
    PACK2(H2,  0.5f, 0.5f);
    PACK2(B02, b0, b2);
    PACK2(B13, b1, b3);
    PACK2(R02, r0, r2);
    PACK2(L13, l1, l3);

    // Per-element thresholds. Lane 31 elem 3 is the nonexistent dual index
    // 127: clamp(+/-MAX) forces n3 = x3 - x3 = 0 exactly, so y127 == 0
    // invariantly and its garbage halo/coefficients never propagate.
    float thr0 = step0 * C_RAMP;
    float thr1 = step1 * C_RAMP;
    float thr2 = step2 * C_RAMP;
    float thr3 = (lane == 31) ? FLT_MAX : step3 * C_RAMP;

    // State: packed even/odd y and nu, plus scalar views of y.
    unsigned long long yyE = 0ull, yyO = 0ull;     // (y0,y2), (y1,y3)
    unsigned long long nuE = 0ull, nuO = 0ull;     // (nu0,nu2), (nu1,nu3)
    float y0 = 0.f, y1 = 0.f, y2 = 0.f, y3 = 0.f;
    float ylm = 0.f, yrp = 0.f;     // y-halos: y[4l-1], y[4l+4]
    float kf = 0.f;                 // iterations since (re)start, as float

    const bool lane0 = (lane == 0);

    // One iteration; B12=(1+beta,..), NB2=(-beta,..) block-constant.
    // TRACK=true returns the prox-gradient residual RES = max_i |n_i - y_i|.
    #define FISTA_STEP(TRACK, RES, B12, NB2)                                 \
    {                                                                        \
        unsigned long long xE, xO;                                           \
        FMA2(xE, H2, yyE, B02);                                              \
        FMA2(xE, R02, yyO, xE);                                              \
        FMA2(xO, H2, yyO, B13);                                              \
        FMA2(xO, L13, yyE, xO);                                              \
        float x0, x1, x2, x3;                                                \
        UNPACK2(x0, x2, xE);                                                 \
        UNPACK2(x1, x3, xO);                                                 \
        x0 = fmaf(l0, ylm, x0);                                              \
        x2 = fmaf(l2, y1,  x2);                                              \
        x1 = fmaf(r1, y2,  x1);                                              \
        x3 = fmaf(r3, yrp, x3);                                              \
        /* soft threshold via clamp: n = x - clamp(x, -thr, thr) */          \
        float n0 = x0 - fminf(fmaxf(x0, -thr0), thr0);                       \
        float n1 = x1 - fminf(fmaxf(x1, -thr1), thr1);                       \
        float n2 = x2 - fminf(fmaxf(x2, -thr2), thr2);                       \
        float n3 = x3 - fminf(fmaxf(x3, -thr3), thr3);                       \
        if (TRACK) {                                                         \
            float r01 = fmaxf(fabsf(n0 - y0), fabsf(n1 - y1));               \
            float r23 = fmaxf(fabsf(n2 - y2), fabsf(n3 - y3));               \
            RES = fmaxf(r01, r23);                                           \
        }                                                                    \
        /* momentum: y = (1+beta)*n + (-beta)*nu  (packed f32x2) */          \
        unsigned long long nE, nO, tE, tO;                                   \
        PACK2(nE, n0, n2);  PACK2(nO, n1, n3);                               \
        MUL2(tE, NB2, nuE);  MUL2(tO, NB2, nuO);                             \
        FMA2(yyE, B12, nE, tE);  FMA2(yyO, B12, nO, tO);                     \
        nuE = nE;  nuO = nO;                                                 \
        UNPACK2(y0, y2, yyE);  UNPACK2(y1, y3, yyO);                         \
        /* y-halos: direct shuffles of the fresh y (garbage at warp edges    \
           is neutralized by l0 = 0 and the lane-31 clamp no-op) */          \
        ylm = __shfl_up_sync  (FULL, y3, 1);                                 \
        yrp = __shfl_down_sync(FULL, y0, 1);                                 \
    }

    float prev_res = FLT_MAX;

    for (int blk = 0; blk < N_BLKS; ++blk) {
        // block-constant beta = kf/(kf+3) at block-start kf (restart -> 0)
        float rk; asm("rcp.approx.f32 %0, %1;" : "=f"(rk) : "f"(kf + 3.0f));
        float beta  = kf * rk;
        float beta1 = 1.0f + beta;
        unsigned long long B12, NB2;
        PACK2(B12, beta1, beta1);
        PACK2(NB2, -beta, -beta);
        kf += (float)BLK_IT;

        float dres;
        #pragma unroll
        for (int j = 0; j < BLK_IT - 1; ++j)
            FISTA_STEP(false, dres, B12, NB2)

        float res;
        FISTA_STEP(true, res, B12, NB2)

        // warp-max of residual: res >= 0 so float bits are order-isomorphic
        float rmax = __uint_as_float(__reduce_max_sync(FULL, __float_as_uint(res)));
        if (rmax < TOL) break;

        // Residual-increase restart (warp-uniform): y = nu, re-shuffle halos.
        if (rmax > prev_res) {
            kf = 0.0f;
            yyE = nuE;  yyO = nuO;
            UNPACK2(y0, y2, yyE);
            UNPACK2(y1, y3, yyO);
            ylm = __shfl_up_sync  (FULL, y3, 1);
            yrp = __shfl_down_sync(FULL, y0, 1);
        }
        prev_res = rmax;
    }

    // z* from the FINAL nu: z_i = pn_i - m_i*(nu_i - nu_{i-1})
    float nu0, nu1, nu2, nu3;
    UNPACK2(nu0, nu2, nuE);
    UNPACK2(nu1, nu3, nuO);
    float num = __shfl_up_sync(FULL, nu3, 1);
    if (lane0) num = 0.0f;
    float4 o4;
    o4.x = fmaf(num - nu0, m0, pn0);
    o4.y = fmaf(nu0 - nu1, m1, pn1);
    o4.z = fmaf(nu1 - nu2, m2, pn2);
    o4.w = fmaf(nu2 - nu3, m3, pn3);
    ((float4*)out)[vbase] = o4;
}

extern "C" void kernel_launch(void* const* d_in, const int* in_sizes, int n_in,
                              void* d_out, int out_size)
{
    const float* z0  = (const float*)d_in[0];
    const float* mu  = (const float*)d_in[1];
    const float* dg  = (const float*)d_in[2];
    const float* d2g = (const float*)d_in[3];
    float* out = (float*)d_out;

    dim3 block(128);
    dim3 grid((BATCH * 32) / 128);   // 1024 blocks, 4 warps each
    fista_warp_kernel<<<grid, block>>>(z0, mu, dg, d2g, out);
}

// round 14
// speedup vs baseline: 1.2723x; 1.0021x over previous
#include <cuda_runtime.h>
#include <float.h>

// Batched Jacobi-preconditioned FISTA (+ residual-increase restart) on the
// dual of a ramp-constrained QP. One warp per batch item; 4 elements/lane,
// paired EVEN/ODD for natural f32x2 stencil operands. Per-element Jacobi
// steps step_i = 0.5/(m_i + m_{i+1}); diagonal stencil coeff exactly 0.5.
// y-halos shuffled directly at end of iteration. beta_k = k/(k+3).
// 32-thread blocks (1 warp/CTA) for near-perfect per-SM wave balance.
#define BATCH   4096
#define NDIM    128
#define C_RAMP  0.5f
#define N_BLKS  500     // 500 * 8 = 4000 iterations max (matches reference)
#define BLK_IT  8
#define TOL     5.5e-4f // prox-gradient residual (inf-norm) for early exit

#define PACK2(out, lo, hi) \
    asm("mov.b64 %0, {%1, %2};" : "=l"(out) : "r"(__float_as_uint(lo)), "r"(__float_as_uint(hi)))
#define UNPACK2(lo, hi, in) do {                                          \
    unsigned _ulo, _uhi;                                                  \
    asm("mov.b64 {%0, %1}, %2;" : "=r"(_ulo), "=r"(_uhi) : "l"(in));      \
    lo = __uint_as_float(_ulo); hi = __uint_as_float(_uhi); } while (0)
#define MUL2(out, a, b) \
    asm("mul.rn.f32x2 %0, %1, %2;" : "=l"(out) : "l"(a), "l"(b))
#define FMA2(out, a, b, c) \
    asm("fma.rn.f32x2 %0, %1, %2, %3;" : "=l"(out) : "l"(a), "l"(b), "l"(c))

__global__ __launch_bounds__(32)
void fista_warp_kernel(const float* __restrict__ z0,
                       const float* __restrict__ mu,
                       const float* __restrict__ dg,
                       const float* __restrict__ d2g,
                       float* __restrict__ out)
{
    const unsigned FULL = 0xffffffffu;
    int gwarp = blockIdx.x;          // one warp per CTA per batch item
    int lane  = threadIdx.x;

    size_t vbase = (size_t)gwarp * (NDIM / 4) + lane;
    float4 z4 = ((const float4*)z0)[vbase];
    float4 m4v = ((const float4*)mu)[vbase];
    float4 g4 = ((const float4*)dg)[vbase];
    float4 h4 = ((const float4*)d2g)[vbase];

    // d = d2g + 1 ; p = dg - d2g*z0 - mu ; m = 1/d ; pn = -p*m  (pn = z(0))
    float d0 = h4.x + 1.0f, d1 = h4.y + 1.0f, d2 = h4.z + 1.0f, d3 = h4.w + 1.0f;
    float p0 = fmaf(-h4.x, z4.x, g4.x) - m4v.x;
    float p1 = fmaf(-h4.y, z4.y, g4.y) - m4v.y;
    float p2 = fmaf(-h4.z, z4.z, g4.z) - m4v.z;
    float p3 = fmaf(-h4.w, z4.w, g4.w) - m4v.w;
    float m0 = 1.0f / d0, m1 = 1.0f / d1, m2 = 1.0f / d2, m3 = 1.0f / d3;
    float pn0 = -p0 * m0, pn1 = -p1 * m1, pn2 = -p2 * m2, pn3 = -p3 * m3;

    // Right-neighbor constants (element 4l+4 of this item).
    float m4n = __shfl_down_sync(FULL, m0, 1);
    float pn4 = __shfl_down_sync(FULL, pn0, 1);

    // Jacobi-preconditioned steps: step_i = 0.5/(m_i + m_{i+1}).
    // Valid: A = D M D^T is diagonally dominant => A <= 2 diag(A).
    float step0 = 0.5f / (m0 + m1);
    float step1 = 0.5f / (m1 + m2);
    float step2 = 0.5f / (m2 + m3);
    float step3 = 0.5f / (m3 + m4n);

    // Stencil: x_i = 0.5*y_i + l_i*y_{i-1} + r_i*y_{i+1} + b_i
    float l0 = (lane == 0) ? 0.0f : step0 * m0;   // y_{-1} = 0 & kills garbage
    float l1 = step1 * m1;
    float l2 = step2 * m2;
    float l3 = step3 * m3;
    float r0 = step0 * m1;
    float r1 = step1 * m2;
    float r2 = step2 * m3;
    float r3 = step3 * m4n;
    float b0 = step0 * (pn0 - pn1);
    float b1 = step1 * (pn1 - pn2);
    float b2 = step2 * (pn2 - pn3);
    float b3 = step3 * (pn3 - pn4);

    // Packed stencil constants on even/odd pairs:
    //   xE=(x0,x2): 0.5*(y0,y2) + (r0,r2)*(y1,y3) + [scalar l0*ylm, l2*y1] + (b0,b2)
    //   xO=(x1,x3): 0.5*(y1,y3) + (l1,l3)*(y0,y2) + [scalar r1*y2, r3*yrp] + (b1,b3)
    unsigned long long H2, B02, B13, R02, L13;
    PACK2(H2,  0.5f, 0.5f);
    PACK2(B02, b0, b2);
    PACK2(B13, b1, b3);
    PACK2(R02, r0, r2);
    PACK2(L13, l1, l3);

    // Per-element thresholds. Lane 31 elem 3 is the nonexistent dual index
    // 127: clamp(+/-MAX) forces n3 = x3 - x3 = 0 exactly, so y127 == 0
    // invariantly and its garbage halo/coefficients never propagate.
    float thr0 = step0 * C_RAMP;
    float thr1 = step1 * C_RAMP;
    float thr2 = step2 * C_RAMP;
    float thr3 = (lane == 31) ? FLT_MAX : step3 * C_RAMP;

    // State: packed even/odd y and nu, plus scalar views of y.
    unsigned long long yyE = 0ull, yyO = 0ull;     // (y0,y2), (y1,y3)
    unsigned long long nuE = 0ull, nuO = 0ull;     // (nu0,nu2), (nu1,nu3)
    float y0 = 0.f, y1 = 0.f, y2 = 0.f, y3 = 0.f;
    float ylm = 0.f, yrp = 0.f;     // y-halos: y[4l-1], y[4l+4]
    float kf = 0.f;                 // iterations since (re)start, as float

    const bool lane0 = (lane == 0);

    // One iteration; B12=(1+beta,..), NB2=(-beta,..) block-constant.
    // TRACK=true returns the prox-gradient residual RES = max_i |n_i - y_i|.
    #define FISTA_STEP(TRACK, RES, B12, NB2)                                 \
    {                                                                        \
        unsigned long long xE, xO;                                           \
        FMA2(xE, H2, yyE, B02);                                              \
        FMA2(xE, R02, yyO, xE);                                              \
        FMA2(xO, H2, yyO, B13);                                              \
        FMA2(xO, L13, yyE, xO);                                              \
        float x0, x1, x2, x3;                                                \
        UNPACK2(x0, x2, xE);                                                 \
        UNPACK2(x1, x3, xO);                                                 \
        x0 = fmaf(l0, ylm, x0);                                              \
        x2 = fmaf(l2, y1,  x2);                                              \
        x1 = fmaf(r1, y2,  x1);                                              \
        x3 = fmaf(r3, yrp, x3);                                              \
        /* soft threshold via clamp: n = x - clamp(x, -thr, thr) */          \
        float n0 = x0 - fminf(fmaxf(x0, -thr0), thr0);                       \
        float n1 = x1 - fminf(fmaxf(x1, -thr1), thr1);                       \
        float n2 = x2 - fminf(fmaxf(x2, -thr2), thr2);                       \
        float n3 = x3 - fminf(fmaxf(x3, -thr3), thr3);                       \
        if (TRACK) {                                                         \
            float r01 = fmaxf(fabsf(n0 - y0), fabsf(n1 - y1));               \
            float r23 = fmaxf(fabsf(n2 - y2), fabsf(n3 - y3));               \
            RES = fmaxf(r01, r23);                                           \
        }                                                                    \
        /* momentum: y = (1+beta)*n + (-beta)*nu  (packed f32x2) */          \
        unsigned long long nE, nO, tE, tO;                                   \
        PACK2(nE, n0, n2);  PACK2(nO, n1, n3);                               \
        MUL2(tE, NB2, nuE);  MUL2(tO, NB2, nuO);                             \
        FMA2(yyE, B12, nE, tE);  FMA2(yyO, B12, nO, tO);                     \
        nuE = nE;  nuO = nO;                                                 \
        UNPACK2(y0, y2, yyE);  UNPACK2(y1, y3, yyO);                         \
        /* y-halos: direct shuffles of the fresh y (garbage at warp edges    \
           is neutralized by l0 = 0 and the lane-31 clamp no-op) */          \
        ylm = __shfl_up_sync  (FULL, y3, 1);                                 \
        yrp = __shfl_down_sync(FULL, y0, 1);                                 \
    }

    float prev_res = FLT_MAX;

    for (int blk = 0; blk < N_BLKS; ++blk) {
        // block-constant beta = kf/(kf+3) at block-start kf (restart -> 0)
        float rk; asm("rcp.approx.f32 %0, %1;" : "=f"(rk) : "f"(kf + 3.0f));
        float beta  = kf * rk;
        float beta1 = 1.0f + beta;
        unsigned long long B12, NB2;
        PACK2(B12, beta1, beta1);
        PACK2(NB2, -beta, -beta);
        kf += (float)BLK_IT;

        float dres;
        #pragma unroll
        for (int j = 0; j < BLK_IT - 1; ++j)
            FISTA_STEP(false, dres, B12, NB2)

        float res;
        FISTA_STEP(true, res, B12, NB2)

        // warp-max of residual: res >= 0 so float bits are order-isomorphic
        float rmax = __uint_as_float(__reduce_max_sync(FULL, __float_as_uint(res)));
        if (rmax < TOL) break;

        // Residual-increase restart (warp-uniform): y = nu, re-shuffle halos.
        if (rmax > prev_res) {
            kf = 0.0f;
            yyE = nuE;  yyO = nuO;
            UNPACK2(y0, y2, yyE);
            UNPACK2(y1, y3, yyO);
            ylm = __shfl_up_sync  (FULL, y3, 1);
            yrp = __shfl_down_sync(FULL, y0, 1);
        }
        prev_res = rmax;
    }

    // z* from the FINAL nu: z_i = pn_i - m_i*(nu_i - nu_{i-1})
    float nu0, nu1, nu2, nu3;
    UNPACK2(nu0, nu2, nuE);
    UNPACK2(nu1, nu3, nuO);
    float num = __shfl_up_sync(FULL, nu3, 1);
    if (lane0) num = 0.0f;
    float4 o4;
    o4.x = fmaf(num - nu0, m0, pn0);
    o4.y = fmaf(nu0 - nu1, m1, pn1);
    o4.z = fmaf(nu1 - nu2, m2, pn2);
    o4.w = fmaf(nu2 - nu3, m3, pn3);
    ((float4*)out)[vbase] = o4;
}

extern "C" void kernel_launch(void* const* d_in, const int* in_sizes, int n_in,
                              void* d_out, int out_size)
{
    const float* z0  = (const float*)d_in[0];
    const float* mu  = (const float*)d_in[1];
    const float* dg  = (const float*)d_in[2];
    const float* d2g = (const float*)d_in[3];
    float* out = (float*)d_out;

    // One warp per CTA: 4096 CTAs over 148 SMs -> 27/28 CTA split per SM
    // (3.5% wave imbalance vs 14% with 4-warp CTAs).
    dim3 block(32);
    dim3 grid(BATCH);
    fista_warp_kernel<<<grid, block>>>(z0, mu, dg, d2g, out);
}

// round 15
// speedup vs baseline: 1.2916x; 1.0151x over previous
#include <cuda_runtime.h>
#include <float.h>

// Batched Jacobi-preconditioned FISTA (+ hysteresis residual restart) on the
// dual of a ramp-constrained QP. One warp per batch item; 4 elements/lane,
// paired EVEN/ODD for natural f32x2 stencil operands. Per-element Jacobi
// steps step_i = 0.5/(m_i + m_{i+1}); diagonal stencil coeff exactly 0.5.
// y-halos shuffled directly at end of iteration. beta_k = k/(k+3).
// 32-thread blocks (1 warp/CTA) for near-perfect per-SM wave balance.
// Restart fires only on a >1.25x residual rise (ripple-tolerant), so hard
// items keep their momentum buildup instead of resetting on noise.
#define BATCH   4096
#define NDIM    128
#define C_RAMP  0.5f
#define N_BLKS  500     // 500 * 8 = 4000 iterations max (matches reference)
#define BLK_IT  8
#define TOL     5.5e-4f // prox-gradient residual (inf-norm) for early exit
#define RST_HYST 1.25f  // restart only if residual rose by this factor

#define PACK2(out, lo, hi) \
    asm("mov.b64 %0, {%1, %2};" : "=l"(out) : "r"(__float_as_uint(lo)), "r"(__float_as_uint(hi)))
#define UNPACK2(lo, hi, in) do {                                          \
    unsigned _ulo, _uhi;                                                  \
    asm("mov.b64 {%0, %1}, %2;" : "=r"(_ulo), "=r"(_uhi) : "l"(in));      \
    lo = __uint_as_float(_ulo); hi = __uint_as_float(_uhi); } while (0)
#define MUL2(out, a, b) \
    asm("mul.rn.f32x2 %0, %1, %2;" : "=l"(out) : "l"(a), "l"(b))
#define FMA2(out, a, b, c) \
    asm("fma.rn.f32x2 %0, %1, %2, %3;" : "=l"(out) : "l"(a), "l"(b), "l"(c))

__global__ __launch_bounds__(32)
void fista_warp_kernel(const float* __restrict__ z0,
                       const float* __restrict__ mu,
                       const float* __restrict__ dg,
                       const float* __restrict__ d2g,
                       float* __restrict__ out)
{
    const unsigned FULL = 0xffffffffu;
    int gwarp = blockIdx.x;          // one warp per CTA per batch item
    int lane  = threadIdx.x;

    size_t vbase = (size_t)gwarp * (NDIM / 4) + lane;
    float4 z4 = ((const float4*)z0)[vbase];
    float4 m4v = ((const float4*)mu)[vbase];
    float4 g4 = ((const float4*)dg)[vbase];
    float4 h4 = ((const float4*)d2g)[vbase];

    // d = d2g + 1 ; p = dg - d2g*z0 - mu ; m = 1/d ; pn = -p*m  (pn = z(0))
    float d0 = h4.x + 1.0f, d1 = h4.y + 1.0f, d2 = h4.z + 1.0f, d3 = h4.w + 1.0f;
    float p0 = fmaf(-h4.x, z4.x, g4.x) - m4v.x;
    float p1 = fmaf(-h4.y, z4.y, g4.y) - m4v.y;
    float p2 = fmaf(-h4.z, z4.z, g4.z) - m4v.z;
    float p3 = fmaf(-h4.w, z4.w, g4.w) - m4v.w;
    float m0 = 1.0f / d0, m1 = 1.0f / d1, m2 = 1.0f / d2, m3 = 1.0f / d3;
    float pn0 = -p0 * m0, pn1 = -p1 * m1, pn2 = -p2 * m2, pn3 = -p3 * m3;

    // Right-neighbor constants (element 4l+4 of this item).
    float m4n = __shfl_down_sync(FULL, m0, 1);
    float pn4 = __shfl_down_sync(FULL, pn0, 1);

    // Jacobi-preconditioned steps: step_i = 0.5/(m_i + m_{i+1}).
    // Valid: A = D M D^T is diagonally dominant => A <= 2 diag(A).
    float step0 = 0.5f / (m0 + m1);
    float step1 = 0.5f / (m1 + m2);
    float step2 = 0.5f / (m2 + m3);
    float step3 = 0.5f / (m3 + m4n);

    // Stencil: x_i = 0.5*y_i + l_i*y_{i-1} + r_i*y_{i+1} + b_i
    float l0 = (lane == 0) ? 0.0f : step0 * m0;   // y_{-1} = 0 & kills garbage
    float l1 = step1 * m1;
    float l2 = step2 * m2;
    float l3 = step3 * m3;
    float r0 = step0 * m1;
    float r1 = step1 * m2;
    float r2 = step2 * m3;
    float r3 = step3 * m4n;
    float b0 = step0 * (pn0 - pn1);
    float b1 = step1 * (pn1 - pn2);
    float b2 = step2 * (pn2 - pn3);
    float b3 = step3 * (pn3 - pn4);

    // Packed stencil constants on even/odd pairs:
    //   xE=(x0,x2): 0.5*(y0,y2) + (r0,r2)*(y1,y3) + [scalar l0*ylm, l2*y1] + (b0,b2)
    //   xO=(x1,x3): 0.5*(y1,y3) + (l1,l3)*(y0,y2) + [scalar r1*y2, r3*yrp] + (b1,b3)
    unsigned long long H2, B02, B13, R02, L13;
    PACK2(H2,  0.5f, 0.5f);
    PACK2(B02, b0, b2);
    PACK2(B13, b1, b3);
    PACK2(R02, r0, r2);
    PACK2(L13, l1, l3);

    // Per-element thresholds. Lane 31 elem 3 is the nonexistent dual index
    // 127: clamp(+/-MAX) forces n3 = x3 - x3 = 0 exactly, so y127 == 0
    // invariantly and its garbage halo/coefficients never propagate.
    float thr0 = step0 * C_RAMP;
    float thr1 = step1 * C_RAMP;
    float thr2 = step2 * C_RAMP;
    float thr3 = (lane == 31) ? FLT_MAX : step3 * C_RAMP;

    // State: packed even/odd y and nu, plus scalar views of y.
    unsigned long long yyE = 0ull, yyO = 0ull;     // (y0,y2), (y1,y3)
    unsigned long long nuE = 0ull, nuO = 0ull;     // (nu0,nu2), (nu1,nu3)
    float y0 = 0.f, y1 = 0.f, y2 = 0.f, y3 = 0.f;
    float ylm = 0.f, yrp = 0.f;     // y-halos: y[4l-1], y[4l+4]
    float kf = 0.f;                 // iterations since (re)start, as float

    const bool lane0 = (lane == 0);

    // One iteration; B12=(1+beta,..), NB2=(-beta,..) block-constant.
    // TRACK=true returns the prox-gradient residual RES = max_i |n_i - y_i|.
    #define FISTA_STEP(TRACK, RES, B12, NB2)                                 \
    {                                                                        \
        unsigned long long xE, xO;                                           \
        FMA2(xE, H2, yyE, B02);                                              \
        FMA2(xE, R02, yyO, xE);                                              \
        FMA2(xO, H2, yyO, B13);                                              \
        FMA2(xO, L13, yyE, xO);                                              \
        float x0, x1, x2, x3;                                                \
        UNPACK2(x0, x2, xE);                                                 \
        UNPACK2(x1, x3, xO);                                                 \
        x0 = fmaf(l0, ylm, x0);                                              \
        x2 = fmaf(l2, y1,  x2);                                              \
        x1 = fmaf(r1, y2,  x1);                                              \
        x3 = fmaf(r3, yrp, x3);                                              \
        /* soft threshold via clamp: n = x - clamp(x, -thr, thr) */          \
        float n0 = x0 - fminf(fmaxf(x0, -thr0), thr0);                       \
        float n1 = x1 - fminf(fmaxf(x1, -thr1), thr1);                       \
        float n2 = x2 - fminf(fmaxf(x2, -thr2), thr2);                       \
        float n3 = x3 - fminf(fmaxf(x3, -thr3), thr3);                       \
        if (TRACK) {                                                         \
            float r01 = fmaxf(fabsf(n0 - y0), fabsf(n1 - y1));               \
            float r23 = fmaxf(fabsf(n2 - y2), fabsf(n3 - y3));               \
            RES = fmaxf(r01, r23);                                           \
        }                                                                    \
        /* momentum: y = (1+beta)*n + (-beta)*nu  (packed f32x2) */          \
        unsigned long long nE, nO, tE, tO;                                   \
        PACK2(nE, n0, n2);  PACK2(nO, n1, n3);                               \
        MUL2(tE, NB2, nuE);  MUL2(tO, NB2, nuO);                             \
        FMA2(yyE, B12, nE, tE);  FMA2(yyO, B12, nO, tO);                     \
        nuE = nE;  nuO = nO;                                                 \
        UNPACK2(y0, y2, yyE);  UNPACK2(y1, y3, yyO);                         \
        /* y-halos: direct shuffles of the fresh y (garbage at warp edges    \
           is neutralized by l0 = 0 and the lane-31 clamp no-op) */          \
        ylm = __shfl_up_sync  (FULL, y3, 1);                                 \
        yrp = __shfl_down_sync(FULL, y0, 1);                                 \
    }

    float prev_res = FLT_MAX;

    for (int blk = 0; blk < N_BLKS; ++blk) {
        // block-constant beta = kf/(kf+3) at block-start kf (restart -> 0)
        float rk; asm("rcp.approx.f32 %0, %1;" : "=f"(rk) : "f"(kf + 3.0f));
        float beta  = kf * rk;
        float beta1 = 1.0f + beta;
        unsigned long long B12, NB2;
        PACK2(B12, beta1, beta1);
        PACK2(NB2, -beta, -beta);
        kf += (float)BLK_IT;

        float dres;
        #pragma unroll
        for (int j = 0; j < BLK_IT - 1; ++j)
            FISTA_STEP(false, dres, B12, NB2)

        float res;
        FISTA_STEP(true, res, B12, NB2)

        // warp-max of residual: res >= 0 so float bits are order-isomorphic
        float rmax = __uint_as_float(__reduce_max_sync(FULL, __float_as_uint(res)));
        if (rmax < TOL) break;

        // Hysteresis restart (warp-uniform): only a >25% residual rise is a
        // genuine momentum blow-up; small ripples keep their momentum.
        if (rmax > RST_HYST * prev_res) {
            kf = 0.0f;
            yyE = nuE;  yyO = nuO;
            UNPACK2(y0, y2, yyE);
            UNPACK2(y1, y3, yyO);
            ylm = __shfl_up_sync  (FULL, y3, 1);
            yrp = __shfl_down_sync(FULL, y0, 1);
        }
        prev_res = rmax;
    }

    // z* from the FINAL nu: z_i = pn_i - m_i*(nu_i - nu_{i-1})
    float nu0, nu1, nu2, nu3;
    UNPACK2(nu0, nu2, nuE);
    UNPACK2(nu1, nu3, nuO);
    float num = __shfl_up_sync(FULL, nu3, 1);
    if (lane0) num = 0.0f;
    float4 o4;
    o4.x = fmaf(num - nu0, m0, pn0);
    o4.y = fmaf(nu0 - nu1, m1, pn1);
    o4.z = fmaf(nu1 - nu2, m2, pn2);
    o4.w = fmaf(nu2 - nu3, m3, pn3);
    ((float4*)out)[vbase] = o4;
}

extern "C" void kernel_launch(void* const* d_in, const int* in_sizes, int n_in,
                              void* d_out, int out_size)
{
    const float* z0  = (const float*)d_in[0];
    const float* mu  = (const float*)d_in[1];
    const float* dg  = (const float*)d_in[2];
    const float* d2g = (const float*)d_in[3];
    float* out = (float*)d_out;

    // One warp per CTA: 4096 CTAs over 148 SMs -> 27/28 CTA split per SM
    // (3.5% wave imbalance vs 14% with 4-warp CTAs).
    dim3 block(32);
    dim3 grid(BATCH);
    fista_warp_kernel<<<grid, block>>>(z0, mu, dg, d2g, out);
}